// round 2
// baseline (speedup 1.0000x reference)
#include <cuda_runtime.h>
#include <math.h>

#define NB  8
#define H   12
#define DH  64
#define LV  1568
#define LA  512
#define NCV 392
#define NCA 256
#define ROW 5696
#define OFF_PROBV 0
#define OFF_PROBA 1568
#define OFF_VCLS  2080
#define OFF_ACLS  2848
#define OFF_PRAV  3616
#define OFF_PRVA  5184

// ---------- scratch ----------
__device__ int   g_cidx_v[NB * NCV];   // sorted gathered v-token ids
__device__ float g_w_v[NB * NCV];      // paired weights (d_n_av), sorted alongside
__device__ int   g_cidx_a[NB * NCA];
__device__ float g_w_a[NB * NCA];
__device__ float g_invS_av[NB];
__device__ float g_invS_va[NB];
__device__ float g_probv[NB * NCV];    // prob accumulators, indexed by sorted slot
__device__ float g_proba[NB * NCA];

// ---------- kernel 1: gather weights, sums, SORT index/weight pairs, zero accums ----------
__global__ void kprep(const float* __restrict__ n_attn_av,
                      const float* __restrict__ n_attn_va,
                      const int* __restrict__ ids_v,
                      const int* __restrict__ ids_a,
                      float* __restrict__ out) {
    int n = blockIdx.x, tid = threadIdx.x;
    __shared__ int   key[512];
    __shared__ float val[512];
    __shared__ float red[512];

    // zero the cls region of the output (atomicAdd targets in kmain)
    float* row = out + (size_t)n * ROW;
    for (int j = tid; j < 1536; j += 512) row[OFF_VCLS + j] = 0.f;

    // ---- v side: gather, sum, sort ----
    int   kk = 0x7FFFFFFF;
    float ww = 0.f;
    if (tid < NCV) {
        kk = ids_v[n * LV + tid];
        ww = n_attn_av[n * LV + kk];
        g_probv[n * NCV + tid] = 0.f;
    }
    key[tid] = kk; val[tid] = ww; red[tid] = ww;
    __syncthreads();
    for (int s = 256; s > 0; s >>= 1) {
        if (tid < s) red[tid] += red[tid + s];
        __syncthreads();
    }
    if (tid == 0) g_invS_av[n] = 1.f / red[0];
    // bitonic sort ascending (padding INT_MAX sinks to the end)
    for (int k = 2; k <= 512; k <<= 1)
        for (int j = k >> 1; j > 0; j >>= 1) {
            int ixj = tid ^ j;
            if (ixj > tid) {
                bool up = ((tid & k) == 0);
                int ka = key[tid], kb = key[ixj];
                if ((ka > kb) == up) {
                    key[tid] = kb; key[ixj] = ka;
                    float va = val[tid], vb = val[ixj];
                    val[tid] = vb; val[ixj] = va;
                }
            }
            __syncthreads();
        }
    if (tid < NCV) {
        g_cidx_v[n * NCV + tid] = key[tid];
        g_w_v[n * NCV + tid]    = val[tid];
    }
    __syncthreads();

    // ---- a side: gather, sum, sort ----
    kk = 0x7FFFFFFF; ww = 0.f;
    if (tid < NCA) {
        kk = ids_a[n * LA + tid];
        ww = n_attn_va[n * LA + kk];
        g_proba[n * NCA + tid] = 0.f;
    }
    key[tid] = kk; val[tid] = ww; red[tid] = ww;
    __syncthreads();
    for (int s = 256; s > 0; s >>= 1) {
        if (tid < s) red[tid] += red[tid + s];
        __syncthreads();
    }
    if (tid == 0) g_invS_va[n] = 1.f / red[0];
    for (int k = 2; k <= 512; k <<= 1)
        for (int j = k >> 1; j > 0; j >>= 1) {
            int ixj = tid ^ j;
            if (ixj > tid) {
                bool up = ((tid & k) == 0);
                int ka = key[tid], kb = key[ixj];
                if ((ka > kb) == up) {
                    key[tid] = kb; key[ixj] = ka;
                    float va = val[tid], vb = val[ixj];
                    val[tid] = vb; val[ixj] = va;
                }
            }
            __syncthreads();
        }
    if (tid < NCA) {
        g_cidx_a[n * NCA + tid] = key[tid];
        g_w_a[n * NCA + tid]    = val[tid];
    }
}

// ---------- kernel 2: spu + pos + sigmoid + cls partials ----------
// grid (H, NB, 3): z=0 -> v side L[0:196], z=1 -> v side L[196:392], z=2 -> a side L[0:256]
__global__ void __launch_bounds__(256)
kmain(const float* __restrict__ pos_v_q, const float* __restrict__ pos_v_k,
      const float* __restrict__ pos_a_q, const float* __restrict__ pos_a_k,
      const float* __restrict__ M_av,    const float* __restrict__ M_va,
      const float* __restrict__ spu_a_cls, const float* __restrict__ spu_v_cls,
      float* __restrict__ out) {
    int h = blockIdx.x, n = blockIdx.y, z = blockIdx.z;
    int tid = threadIdx.x;
    int side   = (z == 2) ? 1 : 0;
    int lbase  = (z == 1) ? 196 : 0;
    int Lchunk = side ? NCA : 196;

    __shared__ int   s_off[NCV];    // sorted S-row offsets (row * stride)
    __shared__ float s_wS[NCV];
    __shared__ int   s_colL[256];   // sorted L column ids for this chunk
    __shared__ float s_wL[256];
    __shared__ float s_cls[DH];
    __shared__ float s_red[256];

    int Scnt, stride, clsoff;
    const float *kten, *qten, *M, *cls;
    const int *cidxL; const float *gwL;
    const int *cidxS; const float *gwS;
    float invS_pos, invS_cls;
    float* acc;
    int Lcnt;
    if (side == 0) {
        Scnt = NCA; stride = LV; clsoff = OFF_VCLS; Lcnt = NCV;
        kten = pos_v_k; qten = pos_v_q; M = M_av; cls = spu_a_cls;
        cidxL = g_cidx_v; gwL = g_w_v; cidxS = g_cidx_a; gwS = g_w_a;
        invS_pos = g_invS_va[n]; invS_cls = g_invS_av[n];
        acc = g_probv + n * NCV;
    } else {
        Scnt = NCV; stride = LA; clsoff = OFF_ACLS; Lcnt = NCA;
        kten = pos_a_k; qten = pos_a_q; M = M_va; cls = spu_v_cls;
        cidxL = g_cidx_a; gwL = g_w_a; cidxS = g_cidx_v; gwS = g_w_v;
        invS_pos = g_invS_av[n]; invS_cls = g_invS_va[n];
        acc = g_proba + n * NCA;
    }

    for (int a = tid; a < Scnt; a += 256) {
        s_off[a] = cidxS[n * Scnt + a] * stride;
        s_wS[a]  = gwS[n * Scnt + a];
    }
    if (tid < Lchunk) {
        s_colL[tid] = cidxL[n * Lcnt + lbase + tid];
        s_wL[tid]   = gwL[n * Lcnt + lbase + tid];
    }
    if (tid < DH) s_cls[tid] = cls[(n * H + h) * DH + tid];
    __syncthreads();

    const float* kbase = kten + (size_t)(n * H + h) * (side ? LA : LV) * DH;
    const float* Mbase = M + (size_t)(n * H + h) * (size_t)LA * LV;

    if (tid < Lchunk) {
        int il = s_colL[tid];
        // spu: 64-dot with cls vector
        const float4* krow = (const float4*)(kbase + (size_t)il * DH);
        float spu = 0.f;
        #pragma unroll
        for (int d4 = 0; d4 < DH / 4; d4++) {
            float4 v = krow[d4];
            spu = fmaf(v.x, s_cls[4 * d4 + 0], spu);
            spu = fmaf(v.y, s_cls[4 * d4 + 1], spu);
            spu = fmaf(v.z, s_cls[4 * d4 + 2], spu);
            spu = fmaf(v.w, s_cls[4 * d4 + 3], spu);
        }
        spu *= 0.125f;
        // pos: weighted sum over sorted gathered rows at sorted column il (8-way MLP)
        float p0 = 0.f, p1 = 0.f, p2 = 0.f, p3 = 0.f;
        float p4 = 0.f, p5 = 0.f, p6 = 0.f, p7 = 0.f;
        for (int a = 0; a < Scnt; a += 8) {
            p0 = fmaf(Mbase[s_off[a + 0] + il], s_wS[a + 0], p0);
            p1 = fmaf(Mbase[s_off[a + 1] + il], s_wS[a + 1], p1);
            p2 = fmaf(Mbase[s_off[a + 2] + il], s_wS[a + 2], p2);
            p3 = fmaf(Mbase[s_off[a + 3] + il], s_wS[a + 3], p3);
            p4 = fmaf(Mbase[s_off[a + 4] + il], s_wS[a + 4], p4);
            p5 = fmaf(Mbase[s_off[a + 5] + il], s_wS[a + 5], p5);
            p6 = fmaf(Mbase[s_off[a + 6] + il], s_wS[a + 6], p6);
            p7 = fmaf(Mbase[s_off[a + 7] + il], s_wS[a + 7], p7);
        }
        float posv = (((p0 + p1) + (p2 + p3)) + ((p4 + p5) + (p6 + p7))) * invS_pos;
        float sig = 1.f / (1.f + __expf(posv - spu));
        atomicAdd(&acc[lbase + tid], sig);
    }

    // cls partial: weighted sum of this chunk's gathered q rows
    const float* qbase = qten + (size_t)(n * H + h) * (side ? LA : LV) * DH;
    {
        int g = tid >> 6, d = tid & 63;
        float a2 = 0.f;
        for (int l = g; l < Lchunk; l += 4)
            a2 = fmaf(qbase[(size_t)s_colL[l] * DH + d], s_wL[l], a2);
        s_red[tid] = a2;
        __syncthreads();
        if (tid < DH) {
            float t = s_red[tid] + s_red[64 + tid] + s_red[128 + tid] + s_red[192 + tid];
            atomicAdd(&out[(size_t)n * ROW + clsoff + h * DH + tid], t * invS_cls);
        }
    }
}

// ---------- kernel 3: defaults + scatter + prune ----------
__global__ void kfin(const float* __restrict__ n_attn_av,
                     const float* __restrict__ n_attn_va,
                     const float* __restrict__ u_v,
                     const float* __restrict__ u_a,
                     float* __restrict__ out) {
    int n = blockIdx.x, tid = threadIdx.x;
    float* row = out + (size_t)n * ROW;
    for (int j = tid; j < LV; j += blockDim.x) {
        row[OFF_PROBV + j] = 0.f;
        row[OFF_PRAV + j]  = n_attn_av[n * LV + j];
    }
    for (int j = tid; j < LA; j += blockDim.x) {
        row[OFF_PROBA + j] = 0.f;
        row[OFF_PRVA + j]  = n_attn_va[n * LA + j];
    }
    __syncthreads();
    if (tid < NCV) {
        int pos = g_cidx_v[n * NCV + tid];  // scatter target IS the sorted index
        float p = g_probv[n * NCV + tid] * (1.f / 12.f);
        row[OFF_PROBV + pos] = p;
        row[OFF_PRAV + pos]  = (u_v[n * LV + pos] < p) ? 0.f : n_attn_av[n * LV + pos];
    }
    if (tid < NCA) {
        int pos = g_cidx_a[n * NCA + tid];
        float p = g_proba[n * NCA + tid] * (1.f / 12.f);
        row[OFF_PROBA + pos] = p;
        row[OFF_PRVA + pos]  = (u_a[n * LA + pos] < p) ? 0.f : n_attn_va[n * LA + pos];
    }
}

extern "C" void kernel_launch(void* const* d_in, const int* in_sizes, int n_in,
                              void* d_out, int out_size) {
    const float* pos_v_q   = (const float*)d_in[0];
    const float* pos_v_k   = (const float*)d_in[1];
    const float* pos_a_q   = (const float*)d_in[2];
    const float* pos_a_k   = (const float*)d_in[3];
    const float* M_av      = (const float*)d_in[4];
    const float* M_va      = (const float*)d_in[5];
    const float* n_attn_av = (const float*)d_in[6];
    const float* n_attn_va = (const float*)d_in[7];
    const float* spu_a_cls = (const float*)d_in[8];
    const float* spu_v_cls = (const float*)d_in[9];
    const float* u_v       = (const float*)d_in[10];
    const float* u_a       = (const float*)d_in[11];
    const int*   ids_v     = (const int*)d_in[12];
    const int*   ids_a     = (const int*)d_in[13];
    float* out = (float*)d_out;

    kprep<<<NB, 512>>>(n_attn_av, n_attn_va, ids_v, ids_a, out);
    kmain<<<dim3(H, NB, 3), 256>>>(pos_v_q, pos_v_k, pos_a_q, pos_a_k,
                                   M_av, M_va, spu_a_cls, spu_v_cls, out);
    kfin<<<NB, 512>>>(n_attn_av, n_attn_va, u_v, u_a, out);
}

// round 7
// speedup vs baseline: 1.6338x; 1.6338x over previous
#include <cuda_runtime.h>
#include <math.h>

#define NB  8
#define H   12
#define DH  64
#define LV  1568
#define LA  512
#define NCV 392
#define NCA 256
#define ROW 5696
#define OFF_PROBV 0
#define OFF_PROBA 1568
#define OFF_VCLS  2080
#define OFF_ACLS  2848
#define OFF_PRAV  3616
#define OFF_PRVA  5184

// ---------- scratch ----------
__device__ int   g_cidx_v[NB * NCV];   // sorted gathered v-token ids
__device__ float g_w_v[NB * NCV];      // paired weights, sorted alongside
__device__ int   g_cidx_a[NB * NCA];
__device__ float g_w_a[NB * NCA];
__device__ float g_invS_av[NB];
__device__ float g_invS_va[NB];
__device__ float g_probv[NB * NCV];
__device__ float g_proba[NB * NCA];

// ---------- kernel 1: gather weights, sum, bitonic sort pairs; grid (NB, 2) ----------
__global__ void kprep(const float* __restrict__ n_attn_av,
                      const float* __restrict__ n_attn_va,
                      const int* __restrict__ ids_v,
                      const int* __restrict__ ids_a) {
    int n = blockIdx.x, side = blockIdx.y, tid = threadIdx.x;
    __shared__ int   key[512];
    __shared__ float val[512];
    __shared__ float red[512];

    int cnt   = side ? NCA : NCV;
    int full  = side ? LA : LV;
    const int*   ids = side ? ids_a : ids_v;
    const float* na  = side ? n_attn_va : n_attn_av;

    int   kk = 0x7FFFFFFF;
    float ww = 0.f;
    if (tid < cnt) {
        kk = ids[n * full + tid];
        ww = na[n * full + kk];
        if (side) g_proba[n * NCA + tid] = 0.f;
        else      g_probv[n * NCV + tid] = 0.f;
    }
    key[tid] = kk; val[tid] = ww; red[tid] = ww;
    __syncthreads();
    for (int s = 256; s > 0; s >>= 1) {
        if (tid < s) red[tid] += red[tid + s];
        __syncthreads();
    }
    if (tid == 0) {
        if (side) g_invS_va[n] = 1.f / red[0];
        else      g_invS_av[n] = 1.f / red[0];
    }
    // bitonic sort ascending over 512 slots (INT_MAX padding sinks)
    for (int k = 2; k <= 512; k <<= 1)
        for (int j = k >> 1; j > 0; j >>= 1) {
            int ixj = tid ^ j;
            if (ixj > tid) {
                bool up = ((tid & k) == 0);
                int ka = key[tid], kb = key[ixj];
                if ((ka > kb) == up) {
                    key[tid] = kb; key[ixj] = ka;
                    float va = val[tid], vb = val[ixj];
                    val[tid] = vb; val[ixj] = va;
                }
            }
            __syncthreads();
        }
    if (tid < cnt) {
        if (side) { g_cidx_a[n * NCA + tid] = key[tid]; g_w_a[n * NCA + tid] = val[tid]; }
        else      { g_cidx_v[n * NCV + tid] = key[tid]; g_w_v[n * NCV + tid] = val[tid]; }
    }
}

// ---------- kernel 2: EXACT Round-1 structure, sorted data ----------
// grid (H, NB, 2): z==0 -> v side, z==1 -> a side
__global__ void __launch_bounds__(512, 2)
kmain(const float* __restrict__ pos_v_q, const float* __restrict__ pos_v_k,
      const float* __restrict__ pos_a_q, const float* __restrict__ pos_a_k,
      const float* __restrict__ M_av,    const float* __restrict__ M_va,
      const float* __restrict__ spu_a_cls, const float* __restrict__ spu_v_cls,
      float* __restrict__ out) {
    int h = blockIdx.x, n = blockIdx.y, side = blockIdx.z;
    int tid = threadIdx.x;

    __shared__ int   s_idxL[NCV];
    __shared__ float s_wL[NCV];
    __shared__ int   s_offS[NCV];
    __shared__ float s_wS[NCV];
    __shared__ float s_cls[DH];
    __shared__ float s_red[512];

    int Lcnt, Scnt, Mstride, clsoff;
    const float *kten, *qten, *M, *cls;
    const int *cidxL, *cidxS;
    const float *gwL, *gwS;
    float invS_pos, invS_cls;
    float* acc;
    if (side == 0) {
        Lcnt = NCV; Scnt = NCA; Mstride = LV; clsoff = OFF_VCLS;
        kten = pos_v_k; qten = pos_v_q; M = M_av; cls = spu_a_cls;
        cidxL = g_cidx_v; cidxS = g_cidx_a;
        gwL = g_w_v; gwS = g_w_a;
        invS_pos = g_invS_va[n]; invS_cls = g_invS_av[n];
        acc = g_probv + n * NCV;
    } else {
        Lcnt = NCA; Scnt = NCV; Mstride = LA; clsoff = OFF_ACLS;
        kten = pos_a_k; qten = pos_a_q; M = M_va; cls = spu_v_cls;
        cidxL = g_cidx_a; cidxS = g_cidx_v;
        gwL = g_w_a; gwS = g_w_v;
        invS_pos = g_invS_av[n]; invS_cls = g_invS_va[n];
        acc = g_proba + n * NCA;
    }

    if (tid < Lcnt) {
        s_idxL[tid] = cidxL[n * Lcnt + tid];
        s_wL[tid]   = gwL[n * Lcnt + tid];
    }
    if (tid < Scnt) {
        s_offS[tid] = cidxS[n * Scnt + tid] * Mstride;
        s_wS[tid]   = gwS[n * Scnt + tid];
    }
    if (tid < DH) s_cls[tid] = cls[(n * H + h) * DH + tid];
    __syncthreads();

    const float* kbase = kten + (size_t)(n * H + h) * (side ? LA : LV) * DH;
    const float* Mbase = M + (size_t)(n * H + h) * (size_t)LA * LV;

    if (tid < Lcnt) {
        int il = s_idxL[tid];
        const float4* krow = (const float4*)(kbase + (size_t)il * DH);
        float spu = 0.f;
        #pragma unroll
        for (int d4 = 0; d4 < DH / 4; d4++) {
            float4 v = krow[d4];
            spu = fmaf(v.x, s_cls[4 * d4 + 0], spu);
            spu = fmaf(v.y, s_cls[4 * d4 + 1], spu);
            spu = fmaf(v.z, s_cls[4 * d4 + 2], spu);
            spu = fmaf(v.w, s_cls[4 * d4 + 3], spu);
        }
        spu *= 0.125f;
        float p0 = 0.f, p1 = 0.f, p2 = 0.f, p3 = 0.f;
        for (int a = 0; a < Scnt; a += 4) {
            p0 = fmaf(Mbase[s_offS[a + 0] + il], s_wS[a + 0], p0);
            p1 = fmaf(Mbase[s_offS[a + 1] + il], s_wS[a + 1], p1);
            p2 = fmaf(Mbase[s_offS[a + 2] + il], s_wS[a + 2], p2);
            p3 = fmaf(Mbase[s_offS[a + 3] + il], s_wS[a + 3], p3);
        }
        float posv = ((p0 + p1) + (p2 + p3)) * invS_pos;
        float sig = 1.f / (1.f + __expf(posv - spu));
        atomicAdd(&acc[tid], sig);
    }

    // cls: weighted sum of gathered q rows -> 64 floats, direct store
    const float* qbase = qten + (size_t)(n * H + h) * (side ? LA : LV) * DH;
    {
        int g = tid >> 6, d = tid & 63;
        float a2 = 0.f;
        for (int l = g; l < Lcnt; l += 8)
            a2 = fmaf(qbase[(size_t)s_idxL[l] * DH + d], s_wL[l], a2);
        s_red[tid] = a2;
        __syncthreads();
        if (tid < DH) {
            float t = 0.f;
            #pragma unroll
            for (int gg = 0; gg < 8; gg++) t += s_red[gg * 64 + tid];
            out[(size_t)n * ROW + clsoff + h * DH + tid] = t * invS_cls;
        }
    }
}

// ---------- kernel 3: defaults + scatter + prune ----------
__global__ void kfin(const float* __restrict__ n_attn_av,
                     const float* __restrict__ n_attn_va,
                     const float* __restrict__ u_v,
                     const float* __restrict__ u_a,
                     float* __restrict__ out) {
    int n = blockIdx.x, tid = threadIdx.x;
    float* row = out + (size_t)n * ROW;
    for (int j = tid; j < LV; j += blockDim.x) {
        row[OFF_PROBV + j] = 0.f;
        row[OFF_PRAV + j]  = n_attn_av[n * LV + j];
    }
    for (int j = tid; j < LA; j += blockDim.x) {
        row[OFF_PROBA + j] = 0.f;
        row[OFF_PRVA + j]  = n_attn_va[n * LA + j];
    }
    __syncthreads();
    if (tid < NCV) {
        int pos = g_cidx_v[n * NCV + tid];   // scatter target IS the sorted id
        float p = g_probv[n * NCV + tid] * (1.f / 12.f);
        row[OFF_PROBV + pos] = p;
        row[OFF_PRAV + pos]  = (u_v[n * LV + pos] < p) ? 0.f : n_attn_av[n * LV + pos];
    }
    if (tid < NCA) {
        int pos = g_cidx_a[n * NCA + tid];
        float p = g_proba[n * NCA + tid] * (1.f / 12.f);
        row[OFF_PROBA + pos] = p;
        row[OFF_PRVA + pos]  = (u_a[n * LA + pos] < p) ? 0.f : n_attn_va[n * LA + pos];
    }
}

extern "C" void kernel_launch(void* const* d_in, const int* in_sizes, int n_in,
                              void* d_out, int out_size) {
    const float* pos_v_q   = (const float*)d_in[0];
    const float* pos_v_k   = (const float*)d_in[1];
    const float* pos_a_q   = (const float*)d_in[2];
    const float* pos_a_k   = (const float*)d_in[3];
    const float* M_av      = (const float*)d_in[4];
    const float* M_va      = (const float*)d_in[5];
    const float* n_attn_av = (const float*)d_in[6];
    const float* n_attn_va = (const float*)d_in[7];
    const float* spu_a_cls = (const float*)d_in[8];
    const float* spu_v_cls = (const float*)d_in[9];
    const float* u_v       = (const float*)d_in[10];
    const float* u_a       = (const float*)d_in[11];
    const int*   ids_v     = (const int*)d_in[12];
    const int*   ids_a     = (const int*)d_in[13];
    float* out = (float*)d_out;

    kprep<<<dim3(NB, 2), 512>>>(n_attn_av, n_attn_va, ids_v, ids_a);
    kmain<<<dim3(H, NB, 2), 512>>>(pos_v_q, pos_v_k, pos_a_q, pos_a_k,
                                   M_av, M_va, spu_a_cls, spu_v_cls, out);
    kfin<<<NB, 512>>>(n_attn_av, n_attn_va, u_v, u_a, out);
}